// round 1
// baseline (speedup 1.0000x reference)
#include <cuda_runtime.h>
#include <cstdint>

#define N_NODES  50000
#define N_EDGES  800000
#define HID      128
#define EDGE_D   16
#define N_GRAPHS 64

#define ETILE 128
#define NTILE 32

// ---------------- device scratch (static, no allocation) ----------------
__device__ float g_hAB[(size_t)N_NODES * 256];   // hA | hB  (51.2 MB)
__device__ float g_agg[(size_t)N_NODES * HID];   // scatter target (25.6 MB)
__device__ float g_Wcat[128 * 256];              // [We1a | We1b] rearranged
__device__ float g_pool[N_GRAPHS * HID];
__device__ float g_cnt[N_GRAPHS];
__device__ int   g_row[N_EDGES];
__device__ int   g_col[N_EDGES];
__device__ int   g_batch[N_NODES];
__device__ int   g_is64;

__device__ __forceinline__ float silu_f(float v) {
    return __fdividef(v, 1.0f + __expf(-v));
}

// ---------------- small prep kernels ----------------
__global__ void k_detect(const void* __restrict__ ei) {
    // int64 node indices < 2^31 -> every high word is 0. int32 data almost
    // surely has a nonzero at one of 16 odd positions.
    const unsigned int* p = (const unsigned int*)ei;
    int is64 = 1;
    for (int i = 0; i < 16; i++) if (p[2 * i + 1] != 0u) is64 = 0;
    g_is64 = is64;
}

__global__ void k_cvt_idx(const void* __restrict__ ei, const void* __restrict__ batch) {
    const int i = blockIdx.x * blockDim.x + threadIdx.x;
    const bool is64 = (g_is64 != 0);
    if (i < N_EDGES) {
        if (is64) {
            const long long* p = (const long long*)ei;
            g_row[i] = (int)p[i];
            g_col[i] = (int)p[N_EDGES + i];
        } else {
            const int* p = (const int*)ei;
            g_row[i] = p[i];
            g_col[i] = p[N_EDGES + i];
        }
    }
    if (i < N_NODES) {
        if (is64) g_batch[i] = (int)((const long long*)batch)[i];
        else      g_batch[i] = ((const int*)batch)[i];
    }
}

__global__ void k_zero_agg() {
    const int i = blockIdx.x * blockDim.x + threadIdx.x;
    if (i < (N_NODES * HID) / 4)
        reinterpret_cast<float4*>(g_agg)[i] = make_float4(0.f, 0.f, 0.f, 0.f);
}

__global__ void k_zero_pool() {
    const int i = blockIdx.x * blockDim.x + threadIdx.x;
    if (i < N_GRAPHS * HID) g_pool[i] = 0.f;
    if (i < N_GRAPHS)       g_cnt[i] = 0.f;
}

__global__ void k_prep_wcat(const float* __restrict__ We1) {
    const int i = blockIdx.x * blockDim.x + threadIdx.x;
    if (i < 128 * 256) {
        const int k = i >> 8, c = i & 255;
        g_Wcat[i] = (c < 128) ? We1[k * 128 + c] : We1[(128 + k) * 128 + (c - 128)];
    }
}

// ---------------- node pre-GEMM: g_hAB[n] = h[n] @ [We1a|We1b] (+be1 on cols<128)
__global__ __launch_bounds__(256) void k_node_pre(const float* __restrict__ h,
                                                  const float* __restrict__ be1) {
    __shared__ float a_s[128 * 36];           // h tile, k-major [k][n], pad 36
    const int n0 = blockIdx.x * NTILE;
    const int t = threadIdx.x;
    {
        const int n  = t >> 3;                // 0..31
        const int k4 = t & 7;                 // 0..7
        const int ng = n0 + n;
#pragma unroll
        for (int j = 0; j < 4; j++) {
            const int k = k4 * 16 + j * 4;
            float4 v = make_float4(0.f, 0.f, 0.f, 0.f);
            if (ng < N_NODES) v = *reinterpret_cast<const float4*>(h + (size_t)ng * 128 + k);
            a_s[(k + 0) * 36 + n] = v.x;
            a_s[(k + 1) * 36 + n] = v.y;
            a_s[(k + 2) * 36 + n] = v.z;
            a_s[(k + 3) * 36 + n] = v.w;
        }
    }
    __syncthreads();
    const int cg = t & 31;                    // 32 groups x 8 cols = 256
    const int ng = t >> 5;                    // 8 groups x 4 nodes
    float acc[4][8];
#pragma unroll
    for (int i = 0; i < 4; i++)
#pragma unroll
        for (int j = 0; j < 8; j++) acc[i][j] = 0.f;

    const float* wbase = g_Wcat + cg * 8;
    for (int k = 0; k < 128; k++) {
        const float4 a  = *reinterpret_cast<const float4*>(&a_s[k * 36 + ng * 4]);
        const float4 w0 = __ldg(reinterpret_cast<const float4*>(wbase + k * 256));
        const float4 w1 = __ldg(reinterpret_cast<const float4*>(wbase + k * 256 + 4));
        const float av[4] = {a.x, a.y, a.z, a.w};
        const float wv[8] = {w0.x, w0.y, w0.z, w0.w, w1.x, w1.y, w1.z, w1.w};
#pragma unroll
        for (int i = 0; i < 4; i++)
#pragma unroll
            for (int j = 0; j < 8; j++) acc[i][j] = fmaf(av[i], wv[j], acc[i][j]);
    }
    const int cbase = cg * 8;
    float bias[8];
#pragma unroll
    for (int j = 0; j < 8; j++) bias[j] = (cbase + j < 128) ? __ldg(be1 + cbase + j) : 0.f;
#pragma unroll
    for (int i = 0; i < 4; i++) {
        const int n = n0 + ng * 4 + i;
        if (n < N_NODES) {
            float4 o0 = make_float4(acc[i][0] + bias[0], acc[i][1] + bias[1],
                                    acc[i][2] + bias[2], acc[i][3] + bias[3]);
            float4 o1 = make_float4(acc[i][4] + bias[4], acc[i][5] + bias[5],
                                    acc[i][6] + bias[6], acc[i][7] + bias[7]);
            *reinterpret_cast<float4*>(g_hAB + (size_t)n * 256 + cbase)     = o0;
            *reinterpret_cast<float4*>(g_hAB + (size_t)n * 256 + cbase + 4) = o1;
        }
    }
}

// ---------------- fused edge kernel: gather + K=17 GEMM + SiLU + GEMM2 + SiLU + scatter
#define EDGE_SMEM_FLOATS (16384 + 2048 + 128 + 128 + 16896 + 128 + 128 + 128 + 2048)
#define EDGE_SMEM_BYTES  (EDGE_SMEM_FLOATS * 4)

__global__ __launch_bounds__(512, 1) void k_edge(const float* __restrict__ x,
                                                 const float* __restrict__ ea,
                                                 const float* __restrict__ We1,
                                                 const float* __restrict__ We2,
                                                 const float* __restrict__ be2) {
    extern __shared__ float sm[];
    float* W2_s  = sm;                                    // 16384
    float* W1e_s = W2_s + 16384;                          // 2048 (16x128)
    float* W1r_s = W1e_s + 2048;                          // 128
    float* be2_s = W1r_s + 128;                           // 128
    float* u_s   = be2_s + 128;                           // 128 x 132 = 16896
    float* rad_s = u_s + 16896;                           // 128
    int*   row_s = reinterpret_cast<int*>(rad_s + 128);   // 128
    int*   col_s = row_s + 128;                           // 128
    float* ea_s  = reinterpret_cast<float*>(col_s + 128); // 2048

    const int t  = threadIdx.x;
    const int e0 = blockIdx.x * ETILE;

    for (int i = t; i < 16384; i += 512) W2_s[i] = We2[i];
    for (int i = t; i < 2048; i += 512) {
        W1e_s[i] = We1[257 * 128 + i];
        ea_s[i]  = ea[(size_t)e0 * 16 + i];
    }
    if (t < 128) {
        W1r_s[t] = We1[256 * 128 + t];
        be2_s[t] = be2[t];
        const int e = e0 + t;
        const int r = g_row[e];
        const int c = g_col[e];
        row_s[t] = r;
        col_s[t] = c;
        const float dx = x[r * 3 + 0] - x[c * 3 + 0];
        const float dy = x[r * 3 + 1] - x[c * 3 + 1];
        const float dz = x[r * 3 + 2] - x[c * 3 + 2];
        rad_s[t] = dx * dx + dy * dy + dz * dz;
    }
    __syncthreads();

    // ---- Phase A: t1 = hA[row] + hB[col] + radial*W1r + ea@W1e ; u = silu(t1)
    {
        const int warp  = t >> 5;
        const int lane  = t & 31;
        const int ebase = warp * 8;
        const int co    = lane * 4;
        float4 a4 = *reinterpret_cast<const float4*>(g_hAB + (size_t)row_s[ebase] * 256 + co);
        float4 b4 = *reinterpret_cast<const float4*>(g_hAB + (size_t)col_s[ebase] * 256 + 128 + co);
#pragma unroll
        for (int ii = 0; ii < 8; ii++) {
            float4 na, nb;
            if (ii < 7) {
                na = *reinterpret_cast<const float4*>(g_hAB + (size_t)row_s[ebase + ii + 1] * 256 + co);
                nb = *reinterpret_cast<const float4*>(g_hAB + (size_t)col_s[ebase + ii + 1] * 256 + 128 + co);
            }
            const int e = ebase + ii;
            const float rad = rad_s[e];
            const float4 wr = *reinterpret_cast<const float4*>(W1r_s + co);
            float tx = fmaf(rad, wr.x, a4.x + b4.x);
            float ty = fmaf(rad, wr.y, a4.y + b4.y);
            float tz = fmaf(rad, wr.z, a4.z + b4.z);
            float tw = fmaf(rad, wr.w, a4.w + b4.w);
#pragma unroll
            for (int j = 0; j < 16; j++) {
                const float ej = ea_s[e * 16 + j];
                const float4 w = *reinterpret_cast<const float4*>(W1e_s + j * 128 + co);
                tx = fmaf(ej, w.x, tx);
                ty = fmaf(ej, w.y, ty);
                tz = fmaf(ej, w.z, tz);
                tw = fmaf(ej, w.w, tw);
            }
            *reinterpret_cast<float4*>(u_s + e * 132 + co) =
                make_float4(silu_f(tx), silu_f(ty), silu_f(tz), silu_f(tw));
            if (ii < 7) { a4 = na; b4 = nb; }
        }
    }
    __syncthreads();

    // ---- Phase B: v = silu(u @ W2 + be2); atomic scatter to g_agg[row]
    {
        const int cg = t & 15;   // 16 groups x 8 cols
        const int eg = t >> 4;   // 32 groups x 4 edges
        float acc[4][8];
#pragma unroll
        for (int i = 0; i < 4; i++)
#pragma unroll
            for (int j = 0; j < 8; j++) acc[i][j] = 0.f;

        const float* wb = W2_s + cg * 8;
        const float* ub = u_s + (size_t)eg * 4 * 132;
#pragma unroll 4
        for (int k = 0; k < 128; k++) {
            const float4 w0 = *reinterpret_cast<const float4*>(wb + k * 128);
            const float4 w1 = *reinterpret_cast<const float4*>(wb + k * 128 + 4);
            const float wv[8] = {w0.x, w0.y, w0.z, w0.w, w1.x, w1.y, w1.z, w1.w};
            float av[4];
#pragma unroll
            for (int i = 0; i < 4; i++) av[i] = ub[i * 132 + k];
#pragma unroll
            for (int i = 0; i < 4; i++)
#pragma unroll
                for (int j = 0; j < 8; j++) acc[i][j] = fmaf(av[i], wv[j], acc[i][j]);
        }
        const int cbase = cg * 8;
#pragma unroll
        for (int i = 0; i < 4; i++) {
            const int e = eg * 4 + i;
            float* dst = g_agg + (size_t)row_s[e] * 128 + cbase;
#pragma unroll
            for (int j = 0; j < 8; j++)
                atomicAdd(dst + j, silu_f(acc[i][j] + be2_s[cbase + j]));
        }
    }
}

// ---------------- node MLP + residual + pooled scatter ----------------
#define NODE_SMEM_FLOATS (256 * 36 + 128 * 33 + 32)
#define NODE_SMEM_BYTES  (NODE_SMEM_FLOATS * 4)

__global__ __launch_bounds__(256) void k_node(const float* __restrict__ h,
                                              const float* __restrict__ Wn1,
                                              const float* __restrict__ bn1,
                                              const float* __restrict__ Wn2,
                                              const float* __restrict__ bn2) {
    extern __shared__ float sm[];
    float* a_s = sm;                      // 256 x 36 (k-major [h|agg])
    float* m_s = sm + 256 * 36;           // 128 x 33 (mid, k-major)
    int*   b_s = reinterpret_cast<int*>(sm + 256 * 36 + 128 * 33);

    const int n0 = blockIdx.x * NTILE;
    const int t = threadIdx.x;
    {
        const int n  = t >> 3;
        const int k4 = t & 7;
        const int ng = n0 + n;
#pragma unroll
        for (int j = 0; j < 4; j++) {
            const int k = k4 * 16 + j * 4;
            float4 v = make_float4(0.f, 0.f, 0.f, 0.f);
            float4 w = make_float4(0.f, 0.f, 0.f, 0.f);
            if (ng < N_NODES) {
                v = *reinterpret_cast<const float4*>(h + (size_t)ng * 128 + k);
                w = *reinterpret_cast<const float4*>(g_agg + (size_t)ng * 128 + k);
            }
            a_s[(k + 0) * 36 + n] = v.x;
            a_s[(k + 1) * 36 + n] = v.y;
            a_s[(k + 2) * 36 + n] = v.z;
            a_s[(k + 3) * 36 + n] = v.w;
            a_s[(128 + k + 0) * 36 + n] = w.x;
            a_s[(128 + k + 1) * 36 + n] = w.y;
            a_s[(128 + k + 2) * 36 + n] = w.z;
            a_s[(128 + k + 3) * 36 + n] = w.w;
        }
        if (t < 32) b_s[t] = (n0 + t < N_NODES) ? g_batch[n0 + t] : 0;
    }
    __syncthreads();

    const int cg = t & 31;  // 32 groups x 4 cols
    const int ng = t >> 5;  // 8 groups x 4 nodes
    float acc[4][4];
#pragma unroll
    for (int i = 0; i < 4; i++)
#pragma unroll
        for (int j = 0; j < 4; j++) acc[i][j] = 0.f;

    for (int k = 0; k < 256; k++) {
        float av[4];
#pragma unroll
        for (int i = 0; i < 4; i++) av[i] = a_s[k * 36 + ng * 4 + i];
        const float4 w = __ldg(reinterpret_cast<const float4*>(Wn1 + k * 128 + cg * 4));
        const float wv[4] = {w.x, w.y, w.z, w.w};
#pragma unroll
        for (int i = 0; i < 4; i++)
#pragma unroll
            for (int j = 0; j < 4; j++) acc[i][j] = fmaf(av[i], wv[j], acc[i][j]);
    }
#pragma unroll
    for (int j = 0; j < 4; j++) {
        const int c = cg * 4 + j;
        const float b = __ldg(bn1 + c);
#pragma unroll
        for (int i = 0; i < 4; i++)
            m_s[c * 33 + ng * 4 + i] = silu_f(acc[i][j] + b);
    }
    __syncthreads();

    float acc2[4][4];
#pragma unroll
    for (int i = 0; i < 4; i++)
#pragma unroll
        for (int j = 0; j < 4; j++) acc2[i][j] = 0.f;

    for (int k = 0; k < 128; k++) {
        float av[4];
#pragma unroll
        for (int i = 0; i < 4; i++) av[i] = m_s[k * 33 + ng * 4 + i];
        const float4 w = __ldg(reinterpret_cast<const float4*>(Wn2 + k * 128 + cg * 4));
        const float wv[4] = {w.x, w.y, w.z, w.w};
#pragma unroll
        for (int i = 0; i < 4; i++)
#pragma unroll
            for (int j = 0; j < 4; j++) acc2[i][j] = fmaf(av[i], wv[j], acc2[i][j]);
    }
#pragma unroll
    for (int i = 0; i < 4; i++) {
        const int n = n0 + ng * 4 + i;
        if (n < N_NODES) {
            const int b = b_s[ng * 4 + i];
#pragma unroll
            for (int j = 0; j < 4; j++) {
                const int c = cg * 4 + j;
                const float hn = acc2[i][j] + __ldg(bn2 + c) + a_s[c * 36 + ng * 4 + i];
                atomicAdd(&g_pool[b * 128 + c], hn);
            }
        }
    }
    if (t < 32 && n0 + t < N_NODES) atomicAdd(&g_cnt[b_s[t]], 1.0f);
}

__global__ void k_pool_final(float* __restrict__ out) {
    const int g = blockIdx.x;
    const int c = threadIdx.x;
    const float cnt = fmaxf(g_cnt[g], 1.0f);
    out[g * 128 + c] = g_pool[g * 128 + c] / cnt;
}

// ---------------- launcher ----------------
extern "C" void kernel_launch(void* const* d_in, const int* in_sizes, int n_in,
                              void* d_out, int out_size) {
    const float* h   = (const float*)d_in[0];
    const void*  ei  = d_in[1];
    const float* x   = (const float*)d_in[2];
    const float* ea  = (const float*)d_in[3];
    const void*  bat = d_in[4];
    const float* We1 = (const float*)d_in[5];
    const float* be1 = (const float*)d_in[6];
    const float* We2 = (const float*)d_in[7];
    const float* be2 = (const float*)d_in[8];
    const float* Wn1 = (const float*)d_in[9];
    const float* bn1 = (const float*)d_in[10];
    const float* Wn2 = (const float*)d_in[11];
    const float* bn2 = (const float*)d_in[12];
    float* out = (float*)d_out;

    cudaFuncSetAttribute(k_edge, cudaFuncAttributeMaxDynamicSharedMemorySize, EDGE_SMEM_BYTES);
    cudaFuncSetAttribute(k_node, cudaFuncAttributeMaxDynamicSharedMemorySize, NODE_SMEM_BYTES);

    k_detect<<<1, 1>>>(ei);
    k_cvt_idx<<<(N_EDGES + 255) / 256, 256>>>(ei, bat);
    k_zero_agg<<<(N_NODES * HID / 4 + 255) / 256, 256>>>();
    k_zero_pool<<<(N_GRAPHS * HID + 255) / 256, 256>>>();
    k_prep_wcat<<<(128 * 256 + 255) / 256, 256>>>(We1);
    k_node_pre<<<(N_NODES + NTILE - 1) / NTILE, 256>>>(h, be1);
    k_edge<<<N_EDGES / ETILE, 512, EDGE_SMEM_BYTES>>>(x, ea, We1, We2, be2);
    k_node<<<(N_NODES + NTILE - 1) / NTILE, 256, NODE_SMEM_BYTES>>>(h, Wn1, bn1, Wn2, bn2);
    k_pool_final<<<N_GRAPHS, HID>>>(out);
}